// round 9
// baseline (speedup 1.0000x reference)
#include <cuda_runtime.h>
#include <cuda_fp16.h>
#include <cstdint>

// ============================================================================
// QuantizedLinear: out[1024,4096] = x @ W^T + bias
//   W[o, b*8+j] = centroids[assignments[b*4096 + o], j]
//
// fp16 mma.sync.m16n8k16 (f32 accum). R9: W-dequant fused into the GEMM's
// B-tile smem fill (no g_Bp materialization, no W prep pass). GEMM mainloop/
// fragment layout unchanged from R6/R8 (it sits on the ~12 cyc/HMMA/SMSP
// legacy-mma floor); prep kernel now converts x only.
// ============================================================================

#define M_DIM 1024
#define N_DIM 4096
#define K_DIM 4096
#define BM 128
#define BN 128
#define BK 64                            // 64 k per tile -> 128B fp16 rows
#define STAGES 2
#define NT (K_DIM / BK)                  // 64 k-tiles
#define A_BYTES (BM * 128)               // 16384
#define B_BYTES (BN * 128)               // 16384
#define STAGE_BYTES (A_BYTES + B_BYTES)  // 32768
#define SMEM_TOTAL (STAGES * STAGE_BYTES) // 65536
#define THREADS 128

// fp16 A operand, fragment-friendly permuted layout: row-major [row][K]; each
// 16-k block stored in order {0,1,8,9,2,3,10,11, 4,5,12,13,6,7,14,15}.
__device__ __align__(16) __half g_Ap[(size_t)M_DIM * K_DIM];

// ---------------------------------------------------------------------------
__device__ __forceinline__ uint32_t smem_u32(const void* p) {
    uint32_t a;
    asm("{ .reg .u64 t; cvta.to.shared.u64 t, %1; cvt.u32.u64 %0, t; }"
        : "=r"(a) : "l"(p));
    return a;
}

__device__ __forceinline__ void cp_async16(uint32_t s, const void* g) {
    asm volatile("cp.async.cg.shared.global [%0], [%1], 16;" :: "r"(s), "l"(g));
}
#define CP_COMMIT() asm volatile("cp.async.commit_group;" ::: "memory")
#define CP_WAIT0()  asm volatile("cp.async.wait_group 0;" ::: "memory")

__device__ __forceinline__ void mma_f16(float* c, const uint32_t* a, const uint32_t* b) {
    asm volatile(
        "mma.sync.aligned.m16n8k16.row.col.f32.f16.f16.f32 "
        "{%0,%1,%2,%3}, {%4,%5,%6,%7}, {%8,%9}, {%0,%1,%2,%3};"
        : "+f"(c[0]), "+f"(c[1]), "+f"(c[2]), "+f"(c[3])
        : "r"(a[0]), "r"(a[1]), "r"(a[2]), "r"(a[3]), "r"(b[0]), "r"(b[1]));
}

// ---------------------------------------------------------------------------
// Prep (1024 blocks of 256): x -> g_Ap only. One thread = one 16-k block:
// 4x LDG.128 (64B contiguous) -> 2x STG.128 permuted fp16.
// ---------------------------------------------------------------------------
__global__ void __launch_bounds__(256) prep_kernel(const float* __restrict__ x) {
    int g = blockIdx.x * 256 + threadIdx.x;   // 16-k block index
    int m = g >> 8;                            // 256 blocks per row
    int kb = g & 255;
    const float4* src = reinterpret_cast<const float4*>(
        x + (size_t)m * K_DIM + kb * 16);
    float4 f0 = __ldg(src + 0);   // k0..3
    float4 f1 = __ldg(src + 1);   // k4..7
    float4 f2 = __ldg(src + 2);   // k8..11
    float4 f3 = __ldg(src + 3);   // k12..15
    // chunk h0: {0,1,8,9,2,3,10,11}; chunk h1: {4,5,12,13,6,7,14,15}
    __half2 o0[4], o1[4];
    o0[0] = __floats2half2_rn(f0.x, f0.y);
    o0[1] = __floats2half2_rn(f2.x, f2.y);
    o0[2] = __floats2half2_rn(f0.z, f0.w);
    o0[3] = __floats2half2_rn(f2.z, f2.w);
    o1[0] = __floats2half2_rn(f1.x, f1.y);
    o1[1] = __floats2half2_rn(f3.x, f3.y);
    o1[2] = __floats2half2_rn(f1.z, f1.w);
    o1[3] = __floats2half2_rn(f3.z, f3.w);
    uint4* dst = reinterpret_cast<uint4*>(g_Ap + (size_t)g * 16);
    dst[0] = *reinterpret_cast<uint4*>(o0);
    dst[1] = *reinterpret_cast<uint4*>(o1);
}

// ---------------------------------------------------------------------------
// GEMM: grid (32, 8), 128 threads, warp grid 2(m) x 2(n), warp tile 64x64.
// A tile via cp.async from g_Ap; B tile dequantized in-kernel into smem.
// Smem rows 128B; 16B-chunk swizzle: c ^= (row&3)*2. 2-stage pipeline.
// ---------------------------------------------------------------------------
__device__ __forceinline__ void load_A_tile(uint32_t smem_base, int stage,
                                            const __half* __restrict__ Ab,
                                            int kt, int tid) {
    uint32_t sA = smem_base + stage * STAGE_BYTES;
    const __half* Ag = Ab + kt * BK;
#pragma unroll
    for (int i = 0; i < 8; i++) {            // A: 1024 16B chunks
        int c = tid + i * THREADS;
        int row = c >> 3, ck = c & 7;
        uint32_t dst = sA + row * 128 + (uint32_t)((ck ^ ((row & 3) * 2)) << 4);
        cp_async16(dst, Ag + (size_t)row * K_DIM + ck * 8);
    }
}

// Dequantize the B tile for ktile kt into stage's smem. Thread t owns n-row
// (n0 + t): 8 assignment ids (blocks kt*8..kt*8+7), 8 full centroid rows,
// 8 swizzled STS.128 in the standard permuted-16k chunk layout.
__device__ __forceinline__ void dequant_B_tile(char* dsm, int stage,
                                               const int* __restrict__ assign,
                                               const float* __restrict__ cent,
                                               int n0, int kt, int tid) {
    char* sB = dsm + stage * STAGE_BYTES + A_BYTES;
    const int n = n0 + tid;
    const int* ap = assign + (size_t)(kt * 8) * N_DIM + n;
    int cid[8];
#pragma unroll
    for (int j = 0; j < 8; j++) cid[j] = __ldg(ap + (size_t)j * N_DIM);

    char* row = sB + tid * 128;
    const uint32_t sw = (uint32_t)((tid & 3) * 2);
#pragma unroll
    for (int j = 0; j < 4; j++) {
        const float* c0 = cent + (size_t)cid[2 * j] * 8;
        const float* c1 = cent + (size_t)cid[2 * j + 1] * 8;
        float4 a_lo = __ldg(reinterpret_cast<const float4*>(c0));
        float4 a_hi = __ldg(reinterpret_cast<const float4*>(c0 + 4));
        float4 b_lo = __ldg(reinterpret_cast<const float4*>(c1));
        float4 b_hi = __ldg(reinterpret_cast<const float4*>(c1 + 4));
        // chunk 2j (half 0): {a_lo.xy, b_lo.xy, a_lo.zw, b_lo.zw}
        __half2 o[4];
        o[0] = __floats2half2_rn(a_lo.x, a_lo.y);
        o[1] = __floats2half2_rn(b_lo.x, b_lo.y);
        o[2] = __floats2half2_rn(a_lo.z, a_lo.w);
        o[3] = __floats2half2_rn(b_lo.z, b_lo.w);
        *reinterpret_cast<uint4*>(row + (((uint32_t)(2 * j) ^ sw) << 4)) =
            *reinterpret_cast<uint4*>(o);
        // chunk 2j+1 (half 1): {a_hi.xy, b_hi.xy, a_hi.zw, b_hi.zw}
        o[0] = __floats2half2_rn(a_hi.x, a_hi.y);
        o[1] = __floats2half2_rn(b_hi.x, b_hi.y);
        o[2] = __floats2half2_rn(a_hi.z, a_hi.w);
        o[3] = __floats2half2_rn(b_hi.z, b_hi.w);
        *reinterpret_cast<uint4*>(row + (((uint32_t)(2 * j + 1) ^ sw) << 4)) =
            *reinterpret_cast<uint4*>(o);
    }
}

__global__ void __launch_bounds__(THREADS, 2)
gemm_kernel(const float* __restrict__ bias, float* __restrict__ out,
            const int* __restrict__ assign, const float* __restrict__ cent) {
    extern __shared__ char dsm[];
    const uint32_t smem_base = smem_u32(dsm);
    const int tid = threadIdx.x;
    const int lane = tid & 31;
    const int wid = tid >> 5;                // 0..3
    const int gid = lane >> 2;               // 0..7
    const int tig = lane & 3;                // 0..3
    const int wm0 = (wid >> 1) * 64;         // 2 m-slots of 64
    const int wn0 = (wid & 1) * 64;          // 2 n-slots of 64
    const int m0 = blockIdx.y * BM;
    const int n0 = blockIdx.x * BN;

    const __half* Ab = g_Ap + (size_t)m0 * K_DIM;

    float acc[4][8][4];
#pragma unroll
    for (int mt = 0; mt < 4; mt++)
#pragma unroll
        for (int nt = 0; nt < 8; nt++)
#pragma unroll
            for (int r = 0; r < 4; r++) acc[mt][nt][r] = 0.0f;

    const uint32_t swz_x = (uint32_t)((gid & 3) * 2);
    const uint32_t sub8 = (uint32_t)((tig & 1) << 3);

    // Fragment double buffers (per 16-k block)
    uint32_t af[2][4][4];
    uint32_t bf[2][8][2];

    #define FRAG_LOAD(B, sa, sb, kbl)                                          \
    do {                                                                       \
        const uint32_t coff =                                                  \
            (uint32_t)(((((kbl) * 2 + (tig >> 1)) ^ swz_x) << 4) | sub8);      \
        _Pragma("unroll")                                                      \
        for (int mt = 0; mt < 4; mt++) {                                       \
            int rlo = wm0 + mt * 16 + gid;                                     \
            uint2 lo = *reinterpret_cast<const uint2*>((sa) + rlo * 128 + coff); \
            uint2 hi = *reinterpret_cast<const uint2*>((sa) + (rlo + 8) * 128 + coff); \
            af[B][mt][0] = lo.x; af[B][mt][2] = lo.y;                          \
            af[B][mt][1] = hi.x; af[B][mt][3] = hi.y;                          \
        }                                                                      \
        _Pragma("unroll")                                                      \
        for (int nt = 0; nt < 8; nt++) {                                       \
            int r = wn0 + nt * 8 + gid;                                        \
            uint2 v = *reinterpret_cast<const uint2*>((sb) + r * 128 + coff);  \
            bf[B][nt][0] = v.x; bf[B][nt][1] = v.y;                            \
        }                                                                      \
    } while (0)

    // Prologue: stage 0 <- tile 0 (A via cp.async, B via dequant STS)
    load_A_tile(smem_base, 0, Ab, 0, tid);
    CP_COMMIT();
    dequant_B_tile(dsm, 0, assign, cent, n0, 0, tid);

    for (int kt = 0; kt < NT; kt++) {
        CP_WAIT0();                          // A(kt) resident
        __syncthreads();                     // B(kt) STS drained + visible;
                                             // other stage free everywhere

        if (kt + 1 < NT) {                   // fill freed stage with kt+1
            load_A_tile(smem_base, (kt + 1) & 1, Ab, kt + 1, tid);
            CP_COMMIT();
            dequant_B_tile(dsm, (kt + 1) & 1, assign, cent, n0, kt + 1, tid);
        }

        const char* sa = dsm + (kt & 1) * STAGE_BYTES;
        const char* sb = sa + A_BYTES;

        FRAG_LOAD(0, sa, sb, 0);             // warm kb0
#pragma unroll
        for (int kb = 0; kb < 4; kb++) {     // four 16-k blocks
            if (kb < 3) FRAG_LOAD((kb + 1) & 1, sa, sb, kb + 1);
            const int B = kb & 1;
#pragma unroll
            for (int mt = 0; mt < 4; mt++)
#pragma unroll
                for (int nt = 0; nt < 8; nt++)
                    mma_f16(acc[mt][nt], af[B][mt], bf[B][nt]);
        }
    }

    // Epilogue: c0,c1 -> (row gid, cols tig*2,+1); c2,c3 -> row gid+8.
#pragma unroll
    for (int mt = 0; mt < 4; mt++) {
        int mlo = m0 + wm0 + mt * 16 + gid;
#pragma unroll
        for (int nt = 0; nt < 8; nt++) {
            int n = n0 + wn0 + nt * 8 + tig * 2;
            float bx = __ldg(bias + n);
            float by = __ldg(bias + n + 1);
            float2 v0 = {acc[mt][nt][0] + bx, acc[mt][nt][1] + by};
            float2 v1 = {acc[mt][nt][2] + bx, acc[mt][nt][3] + by};
            *reinterpret_cast<float2*>(out + (size_t)mlo * N_DIM + n) = v0;
            *reinterpret_cast<float2*>(out + (size_t)(mlo + 8) * N_DIM + n) = v1;
        }
    }
}

// ---------------------------------------------------------------------------
extern "C" void kernel_launch(void* const* d_in, const int* in_sizes, int n_in,
                              void* d_out, int out_size) {
    const float* x = nullptr;
    const float* cent = nullptr;
    const float* bias = nullptr;
    const int* assign = nullptr;
    // Inputs by element count: x=4194304, centroids=16384, bias=4096,
    // assignments=2097152, counts=2048 (unused).
    for (int i = 0; i < n_in; i++) {
        switch (in_sizes[i]) {
            case M_DIM * K_DIM:        x = (const float*)d_in[i]; break;
            case 2048 * 8:             cent = (const float*)d_in[i]; break;
            case N_DIM:                bias = (const float*)d_in[i]; break;
            case (K_DIM / 8) * N_DIM:  assign = (const int*)d_in[i]; break;
            default: break;
        }
    }

    static bool attr_done = false;
    if (!attr_done) {
        cudaFuncSetAttribute(gemm_kernel,
                             cudaFuncAttributeMaxDynamicSharedMemorySize, SMEM_TOTAL);
        attr_done = true;
    }

    prep_kernel<<<1024, 256>>>(x);
    gemm_kernel<<<dim3(N_DIM / BN, M_DIM / BM), THREADS, SMEM_TOTAL>>>(
        bias, (float*)d_out, assign, cent);
}

// round 11
// speedup vs baseline: 1.4926x; 1.4926x over previous
#include <cuda_runtime.h>
#include <cuda_fp16.h>
#include <cstdint>

// ============================================================================
// QuantizedLinear: out[1024,4096] = x @ W^T + bias
//   W[o, b*8+j] = centroids[assignments[b*4096 + o], j]
//
// fp16 mma.sync.m16n8k16 (f32 accum). R11 = R10 with the W-pass grid bug
// fixed (512 W-blocks, not 256 — R10 left K in [2048,4096) stale).
// GEMM identical to R8 (~12 cyc/HMMA/SMSP legacy-mma floor). Prep W-pass:
// centroid table staged in smem as fp16, gathers via LDS.64.
// ============================================================================

#define M_DIM 1024
#define N_DIM 4096
#define K_DIM 4096
#define BM 128
#define BN 128
#define BK 64                            // 64 k per tile -> 128B fp16 rows
#define STAGES 2
#define NT (K_DIM / BK)                  // 64 k-tiles
#define A_BYTES (BM * 128)               // 16384
#define B_BYTES (BN * 128)               // 16384
#define STAGE_BYTES (A_BYTES + B_BYTES)  // 32768
#define SMEM_TOTAL (STAGES * STAGE_BYTES) // 65536
#define THREADS 128
#define NCENT 2048
#define XBLOCKS 1024
#define WBLOCKS 512                      // 16 n-slices x 32 k-slices

// fp16 operands, fragment-friendly permuted layout: row-major [row][K]; each
// 16-k block stored in order {0,1,8,9,2,3,10,11, 4,5,12,13,6,7,14,15}.
__device__ __align__(16) __half g_Ap[(size_t)M_DIM * K_DIM];
__device__ __align__(16) __half g_Bp[(size_t)N_DIM * K_DIM];

// ---------------------------------------------------------------------------
__device__ __forceinline__ uint32_t smem_u32(const void* p) {
    uint32_t a;
    asm("{ .reg .u64 t; cvta.to.shared.u64 t, %1; cvt.u32.u64 %0, t; }"
        : "=r"(a) : "l"(p));
    return a;
}

__device__ __forceinline__ void cp_async16(uint32_t s, const void* g) {
    asm volatile("cp.async.cg.shared.global [%0], [%1], 16;" :: "r"(s), "l"(g));
}
#define CP_COMMIT() asm volatile("cp.async.commit_group;" ::: "memory")
#define CP_WAIT0()  asm volatile("cp.async.wait_group 0;" ::: "memory")

__device__ __forceinline__ void mma_f16(float* c, const uint32_t* a, const uint32_t* b) {
    asm volatile(
        "mma.sync.aligned.m16n8k16.row.col.f32.f16.f16.f32 "
        "{%0,%1,%2,%3}, {%4,%5,%6,%7}, {%8,%9}, {%0,%1,%2,%3};"
        : "+f"(c[0]), "+f"(c[1]), "+f"(c[2]), "+f"(c[3])
        : "r"(a[0]), "r"(a[1]), "r"(a[2]), "r"(a[3]), "r"(b[0]), "r"(b[1]));
}

// ---------------------------------------------------------------------------
// Prep (1536 blocks of 256):
//   blocks [0,1024):    x -> g_Ap. One thread = one 16-k block:
//                       4x LDG.128 -> 2x STG.128 permuted fp16.
//   blocks [1024,1536): dequant W -> g_Bp. Block covers 256 n x 128 K.
//                       Centroid table staged in smem as fp16; gathers via
//                       LDS.64; coalesced STG.128 output.
// ---------------------------------------------------------------------------
__global__ void __launch_bounds__(256) prep_kernel(const float* __restrict__ x,
                                                   const int* __restrict__ assign,
                                                   const float* __restrict__ cent) {
    __shared__ __half s_tab[NCENT * 8];       // 32 KB: row = 4x half2 (k0..k7)
    __shared__ int s_cid[16 * 256];           // 16 KB: [in-block][n_local]
    const int b = blockIdx.x;
    const int tid = threadIdx.x;

    if (b < XBLOCKS) {
        int g = b * 256 + tid;                // 16-k block index
        int m = g >> 8;                       // 256 blocks per row
        int kb = g & 255;
        const float4* src = reinterpret_cast<const float4*>(
            x + (size_t)m * K_DIM + kb * 16);
        float4 f0 = __ldg(src + 0);   // k0..3
        float4 f1 = __ldg(src + 1);   // k4..7
        float4 f2 = __ldg(src + 2);   // k8..11
        float4 f3 = __ldg(src + 3);   // k12..15
        __half2 o0[4], o1[4];
        o0[0] = __floats2half2_rn(f0.x, f0.y);
        o0[1] = __floats2half2_rn(f2.x, f2.y);
        o0[2] = __floats2half2_rn(f0.z, f0.w);
        o0[3] = __floats2half2_rn(f2.z, f2.w);
        o1[0] = __floats2half2_rn(f1.x, f1.y);
        o1[1] = __floats2half2_rn(f3.x, f3.y);
        o1[2] = __floats2half2_rn(f1.z, f1.w);
        o1[3] = __floats2half2_rn(f3.z, f3.w);
        uint4* dst = reinterpret_cast<uint4*>(g_Ap + (size_t)g * 16);
        dst[0] = *reinterpret_cast<uint4*>(o0);
        dst[1] = *reinterpret_cast<uint4*>(o1);
    } else {
        const int wb = b - XBLOCKS;           // 0..511
        const int n0 = (wb & 15) * 256;       // 16 n-slices of 256
        const int kb0 = (wb >> 4) * 128;      // 32 k-slices of 128
        const int b0 = kb0 >> 3;              // first of 16 in-blocks

        // Stage centroid table: thread handles rows tid, tid+256, ... (8 rows)
#pragma unroll
        for (int i = 0; i < 8; i++) {
            int r = tid + i * 256;
            float4 lo = __ldg(reinterpret_cast<const float4*>(cent + (size_t)r * 8));
            float4 hi = __ldg(reinterpret_cast<const float4*>(cent + (size_t)r * 8 + 4));
            __half2 h[4];
            h[0] = __floats2half2_rn(lo.x, lo.y);
            h[1] = __floats2half2_rn(lo.z, lo.w);
            h[2] = __floats2half2_rn(hi.x, hi.y);
            h[3] = __floats2half2_rn(hi.z, hi.w);
            *reinterpret_cast<uint4*>(s_tab + r * 8) = *reinterpret_cast<uint4*>(h);
        }
        // Stage assignment ids: 4096 entries, coalesced
#pragma unroll
        for (int i = 0; i < 16; i++) {
            int idx = tid + i * 256;
            int bl = idx >> 8, nl = idx & 255;
            s_cid[bl * 256 + nl] = assign[(size_t)(b0 + bl) * N_DIM + n0 + nl];
        }
        __syncthreads();

        // 4096 output chunks: thread t does chunk (t&15) of rows (t>>4)+16i.
        // Chunk c: t16=c>>1, h=c&1; layout {a(4h,4h+1), b(..), a(4h+2,4h+3), b(..)}
        const int ck = tid & 15;
        const int t16 = ck >> 1;
        const int h = ck & 1;
#pragma unroll
        for (int i = 0; i < 16; i++) {
            int nl = (tid >> 4) + i * 16;
            int cid0 = s_cid[(2 * t16) * 256 + nl];
            int cid1 = s_cid[(2 * t16 + 1) * 256 + nl];
            uint2 a8 = *reinterpret_cast<const uint2*>(s_tab + cid0 * 8 + h * 4);
            uint2 b8 = *reinterpret_cast<const uint2*>(s_tab + cid1 * 8 + h * 4);
            uint4 o = make_uint4(a8.x, b8.x, a8.y, b8.y);
            *reinterpret_cast<uint4*>(
                g_Bp + (size_t)(n0 + nl) * K_DIM + kb0 + ck * 8) = o;
        }
    }
}

// ---------------------------------------------------------------------------
// GEMM (identical to R8): grid (32, 8), 128 threads, warp grid 2(m) x 2(n),
// warp tile 64x64, 2-stage cp.async pipeline, 2 CTAs/SM.
// Smem tile rows 128B; 16B-chunk swizzle: c ^= (row&3)*2.
// ---------------------------------------------------------------------------
__device__ __forceinline__ void load_tile(uint32_t smem_base, int stage,
                                          const __half* __restrict__ Ab,
                                          const __half* __restrict__ Bb,
                                          int kt, int tid) {
    uint32_t sA = smem_base + stage * STAGE_BYTES;
    uint32_t sB = sA + A_BYTES;
    const __half* Ag = Ab + kt * BK;
    const __half* Bg = Bb + kt * BK;
#pragma unroll
    for (int i = 0; i < 8; i++) {            // A: 1024 16B chunks
        int c = tid + i * THREADS;
        int row = c >> 3, ck = c & 7;
        uint32_t dst = sA + row * 128 + (uint32_t)((ck ^ ((row & 3) * 2)) << 4);
        cp_async16(dst, Ag + (size_t)row * K_DIM + ck * 8);
    }
#pragma unroll
    for (int i = 0; i < 8; i++) {            // B: 1024 16B chunks
        int c = tid + i * THREADS;
        int row = c >> 3, ck = c & 7;
        uint32_t dst = sB + row * 128 + (uint32_t)((ck ^ ((row & 3) * 2)) << 4);
        cp_async16(dst, Bg + (size_t)row * K_DIM + ck * 8);
    }
}

__global__ void __launch_bounds__(THREADS, 2)
gemm_kernel(const float* __restrict__ bias, float* __restrict__ out) {
    extern __shared__ char dsm[];
    const uint32_t smem_base = smem_u32(dsm);
    const int tid = threadIdx.x;
    const int lane = tid & 31;
    const int wid = tid >> 5;                // 0..3
    const int gid = lane >> 2;               // 0..7
    const int tig = lane & 3;                // 0..3
    const int wm0 = (wid >> 1) * 64;         // 2 m-slots of 64
    const int wn0 = (wid & 1) * 64;          // 2 n-slots of 64
    const int m0 = blockIdx.y * BM;
    const int n0 = blockIdx.x * BN;

    const __half* Ab = g_Ap + (size_t)m0 * K_DIM;
    const __half* Bb = g_Bp + (size_t)n0 * K_DIM;

    float acc[4][8][4];
#pragma unroll
    for (int mt = 0; mt < 4; mt++)
#pragma unroll
        for (int nt = 0; nt < 8; nt++)
#pragma unroll
            for (int r = 0; r < 4; r++) acc[mt][nt][r] = 0.0f;

    const uint32_t swz_x = (uint32_t)((gid & 3) * 2);
    const uint32_t sub8 = (uint32_t)((tig & 1) << 3);

    // Fragment double buffers (per 16-k block)
    uint32_t af[2][4][4];
    uint32_t bf[2][8][2];

    #define FRAG_LOAD(B, sa, sb, kbl)                                          \
    do {                                                                       \
        const uint32_t coff =                                                  \
            (uint32_t)(((((kbl) * 2 + (tig >> 1)) ^ swz_x) << 4) | sub8);      \
        _Pragma("unroll")                                                      \
        for (int mt = 0; mt < 4; mt++) {                                       \
            int rlo = wm0 + mt * 16 + gid;                                     \
            uint2 lo = *reinterpret_cast<const uint2*>((sa) + rlo * 128 + coff); \
            uint2 hi = *reinterpret_cast<const uint2*>((sa) + (rlo + 8) * 128 + coff); \
            af[B][mt][0] = lo.x; af[B][mt][2] = lo.y;                          \
            af[B][mt][1] = hi.x; af[B][mt][3] = hi.y;                          \
        }                                                                      \
        _Pragma("unroll")                                                      \
        for (int nt = 0; nt < 8; nt++) {                                       \
            int r = wn0 + nt * 8 + gid;                                        \
            uint2 v = *reinterpret_cast<const uint2*>((sb) + r * 128 + coff);  \
            bf[B][nt][0] = v.x; bf[B][nt][1] = v.y;                            \
        }                                                                      \
    } while (0)

    // Prologue: stage 0 <- tile 0
    load_tile(smem_base, 0, Ab, Bb, 0, tid);
    CP_COMMIT();

    for (int kt = 0; kt < NT; kt++) {
        CP_WAIT0();                          // tile kt resident
        __syncthreads();                     // all warps done with other stage

        if (kt + 1 < NT) {                   // load next tile into freed stage
            load_tile(smem_base, (kt + 1) & 1, Ab, Bb, kt + 1, tid);
            CP_COMMIT();
        }

        const char* sa = dsm + (kt & 1) * STAGE_BYTES;
        const char* sb = sa + A_BYTES;

        FRAG_LOAD(0, sa, sb, 0);             // warm kb0
#pragma unroll
        for (int kb = 0; kb < 4; kb++) {     // four 16-k blocks
            if (kb < 3) FRAG_LOAD((kb + 1) & 1, sa, sb, kb + 1);
            const int B = kb & 1;
#pragma unroll
            for (int mt = 0; mt < 4; mt++)
#pragma unroll
                for (int nt = 0; nt < 8; nt++)
                    mma_f16(acc[mt][nt], af[B][mt], bf[B][nt]);
        }
    }

    // Epilogue: c0,c1 -> (row gid, cols tig*2,+1); c2,c3 -> row gid+8.
#pragma unroll
    for (int mt = 0; mt < 4; mt++) {
        int mlo = m0 + wm0 + mt * 16 + gid;
#pragma unroll
        for (int nt = 0; nt < 8; nt++) {
            int n = n0 + wn0 + nt * 8 + tig * 2;
            float bx = __ldg(bias + n);
            float by = __ldg(bias + n + 1);
            float2 v0 = {acc[mt][nt][0] + bx, acc[mt][nt][1] + by};
            float2 v1 = {acc[mt][nt][2] + bx, acc[mt][nt][3] + by};
            *reinterpret_cast<float2*>(out + (size_t)mlo * N_DIM + n) = v0;
            *reinterpret_cast<float2*>(out + (size_t)(mlo + 8) * N_DIM + n) = v1;
        }
    }
}

// ---------------------------------------------------------------------------
extern "C" void kernel_launch(void* const* d_in, const int* in_sizes, int n_in,
                              void* d_out, int out_size) {
    const float* x = nullptr;
    const float* cent = nullptr;
    const float* bias = nullptr;
    const int* assign = nullptr;
    // Inputs by element count: x=4194304, centroids=16384, bias=4096,
    // assignments=2097152, counts=2048 (unused).
    for (int i = 0; i < n_in; i++) {
        switch (in_sizes[i]) {
            case M_DIM * K_DIM:        x = (const float*)d_in[i]; break;
            case 2048 * 8:             cent = (const float*)d_in[i]; break;
            case N_DIM:                bias = (const float*)d_in[i]; break;
            case (K_DIM / 8) * N_DIM:  assign = (const int*)d_in[i]; break;
            default: break;
        }
    }

    static bool attr_done = false;
    if (!attr_done) {
        cudaFuncSetAttribute(gemm_kernel,
                             cudaFuncAttributeMaxDynamicSharedMemorySize, SMEM_TOTAL);
        attr_done = true;
    }

    prep_kernel<<<XBLOCKS + WBLOCKS, 256>>>(x, assign, cent);
    gemm_kernel<<<dim3(N_DIM / BN, M_DIM / BM), THREADS, SMEM_TOTAL>>>(
        bias, (float*)d_out);
}